// round 16
// baseline (speedup 1.0000x reference)
#include <cuda_runtime.h>
#include <cuda_fp16.h>
#include <cstdint>

#define NN 100000
#define NE 1600000
#define D  128
#define CSR_BLOCKS 98   // ceil(NN / 1024); all resident (1 block/SM max on 148 SMs)

// ---------------- scratch (device globals — no allocation allowed) ----------
__device__ __align__(16) int    g_cursor[NN];
__device__ __align__(16) int    g_rowptr[NN + 1];
__device__ __align__(16) int    g_blocksum[CSR_BLOCKS];
__device__ __align__(16) int    g_col[NE];
__device__ int g_sync1, g_sync2, g_sync3;                 // grid-barrier counters
__device__ __align__(16) __half g_hh  [(size_t)NN * D];   // fp16 node features (layer input)
__device__ __align__(16) __half g_aggh[(size_t)NN * D];   // fp16 aggregated features
// fragment-major fp16 weights, paired n-tiles:
// per layer: 16 ksteps x 8 ntile-pairs x 32 lanes x uint4 {b0e,b1e,b0o,b1o}
__device__ __align__(16) uint2  g_wtf [3 * 8192];

// fp16 tensor-core mma, fp32 accumulate (baseline PTX, works on compute_103)
__device__ __forceinline__ void mma_f16(float* c, const uint32_t* a,
                                        uint32_t b0, uint32_t b1) {
    asm volatile(
        "mma.sync.aligned.m16n8k16.row.col.f32.f16.f16.f32 "
        "{%0,%1,%2,%3}, {%4,%5,%6,%7}, {%8,%9}, {%0,%1,%2,%3};"
        : "+f"(c[0]), "+f"(c[1]), "+f"(c[2]), "+f"(c[3])
        : "r"(a[0]), "r"(a[1]), "r"(a[2]), "r"(a[3]), "r"(b0), "r"(b1));
}

__device__ __forceinline__ void ldmatrix_x4(uint32_t* a, uint32_t addr) {
    asm volatile("ldmatrix.sync.aligned.m8n8.x4.shared.b16 {%0,%1,%2,%3}, [%4];"
                 : "=r"(a[0]), "=r"(a[1]), "=r"(a[2]), "=r"(a[3]) : "r"(addr));
}

__device__ __forceinline__ void cp_async16(uint32_t dst, const void* src, int szbytes) {
    asm volatile("cp.async.cg.shared.global [%0], [%1], 16, %2;"
                 :: "r"(dst), "l"(src), "r"(szbytes) : "memory");
}
__device__ __forceinline__ uint32_t smem_u32(const void* p) {
    uint32_t a;
    asm("{ .reg .u64 t; cvta.to.shared.u64 t, %1; cvt.u32.u64 %0, t; }" : "=r"(a) : "l"(p));
    return a;
}

// all-resident grid barrier (counter preset to 0 by cvt_x each call)
__device__ __forceinline__ void grid_barrier(int* ctr) {
    __syncthreads();
    if (threadIdx.x == 0) {
        __threadfence();
        atomicAdd(ctr, 1);
        while (atomicAdd(ctr, 0) < CSR_BLOCKS) __nanosleep(64);
    }
    __syncthreads();
}

// ---------------- x -> fp16 copy (also zeroes cursor + barrier counters) -----
__global__ void cvt_x_kernel(const float* __restrict__ x) {
    int i = blockIdx.x * blockDim.x + threadIdx.x;   // 3.2M threads
    if (i < NN) g_cursor[i] = 0;                     // covers 100K cursor slots
    if (i == 0) { g_sync1 = 0; g_sync2 = 0; g_sync3 = 0; }
    if (i >= NN * D / 4) return;
    float4 v = ((const float4*)x)[i];
    __half2 h0 = __floats2half2_rn(v.x, v.y);
    __half2 h1 = __floats2half2_rn(v.z, v.w);
    ((uint2*)g_hh)[i] = make_uint2(*(uint32_t*)&h0, *(uint32_t*)&h1);
}

// ---------------- fused CSR build: hist + scan + offsets + fill --------------
__global__ void __launch_bounds__(1024, 1)
csr_kernel(const int* __restrict__ ei) {
    const int tid = threadIdx.x;
    const int bid = blockIdx.x;
    const int nth = CSR_BLOCKS * 1024;
    const int gtid = bid * 1024 + tid;

    // ---- phase 1: histogram (int4-vectorized destination reads) ----
    for (int q = gtid; q < NE / 4; q += nth) {
        int4 d = ((const int4*)(ei + NE))[q];
        if ((unsigned)d.x < NN) atomicAdd(&g_cursor[d.x], 1);
        if ((unsigned)d.y < NN) atomicAdd(&g_cursor[d.y], 1);
        if ((unsigned)d.z < NN) atomicAdd(&g_cursor[d.z], 1);
        if ((unsigned)d.w < NN) atomicAdd(&g_cursor[d.w], 1);
    }
    grid_barrier(&g_sync1);

    // ---- phase 2: block-local exclusive scan of this block's 1024 nodes ----
    {
        const int lane = tid & 31;
        const int warp = tid >> 5;
        const int i    = gtid;
        int v = (i < NN) ? __ldcg(&g_cursor[i]) : 0;   // L2 read (atomics live in L2)
        int x = v;
        #pragma unroll
        for (int off = 1; off < 32; off <<= 1) {
            int t = __shfl_up_sync(0xFFFFFFFFu, x, off);
            if (lane >= off) x += t;
        }
        __shared__ int wsum[32];
        if (lane == 31) wsum[warp] = x;
        __syncthreads();
        if (warp == 0) {
            int y = wsum[lane];
            #pragma unroll
            for (int off = 1; off < 32; off <<= 1) {
                int t = __shfl_up_sync(0xFFFFFFFFu, y, off);
                if (lane >= off) y += t;
            }
            wsum[lane] = y;
        }
        __syncthreads();
        int blockExcl = (warp > 0) ? wsum[warp - 1] : 0;
        if (i < NN) g_rowptr[i] = blockExcl + x - v;   // block-local exclusive
        if (tid == 1023) g_blocksum[bid] = blockExcl + x;
    }
    grid_barrier(&g_sync2);

    // ---- phase 3: scan block sums, apply offset, init fill cursor ----
    {
        __shared__ int s[128];
        if (tid < 128) s[tid] = (tid < CSR_BLOCKS) ? __ldcg(&g_blocksum[tid]) : 0;
        __syncthreads();
        #pragma unroll
        for (int off = 1; off < 128; off <<= 1) {
            int t = 0;
            if (tid < 128 && tid >= off) t = s[tid - off];
            __syncthreads();
            if (tid < 128) s[tid] += t;
            __syncthreads();
        }
        int excl = (bid > 0) ? s[bid - 1] : 0;
        int i = gtid;
        if (i < NN) {
            int v = g_rowptr[i] + excl;   // own block's write: L1-safe
            g_rowptr[i] = v;
            g_cursor[i] = v;
        }
        if (bid == CSR_BLOCKS - 1 && tid == 0)
            g_rowptr[NN] = s[CSR_BLOCKS - 1];
    }
    grid_barrier(&g_sync3);

    // ---- phase 4: fill columns (int4-vectorized edge reads) ----
    for (int q = gtid; q < NE / 4; q += nth) {
        int4 s4 = ((const int4*)ei)[q];
        int4 d4 = ((const int4*)(ei + NE))[q];
        if ((unsigned)d4.x < NN && (unsigned)s4.x < NN) g_col[atomicAdd(&g_cursor[d4.x], 1)] = s4.x;
        if ((unsigned)d4.y < NN && (unsigned)s4.y < NN) g_col[atomicAdd(&g_cursor[d4.y], 1)] = s4.y;
        if ((unsigned)d4.z < NN && (unsigned)s4.z < NN) g_col[atomicAdd(&g_cursor[d4.z], 1)] = s4.z;
        if ((unsigned)d4.w < NN && (unsigned)s4.w < NN) g_col[atomicAdd(&g_cursor[d4.w], 1)] = s4.w;
    }
}

// ---------------- weight prep: fragment-major fp16, paired n-tiles -----------
__global__ void prep_wt_kernel(const float* __restrict__ wr1, const float* __restrict__ wo1,
                               const float* __restrict__ wr2, const float* __restrict__ wo2,
                               const float* __restrict__ wr3, const float* __restrict__ wo3) {
    int i = blockIdx.x * blockDim.x + threadIdx.x;   // over 49152 u32 slots
    if (i >= 3 * 16384) return;
    int j2   = i & 3;
    int lane = (i >> 2) & 31;
    int nt2  = (i >> 7) & 7;
    int ksg  = (i >> 10) & 15;
    int l    = i >> 14;
    int ntl  = nt2 * 2 + (j2 >> 1);
    int j    = j2 & 1;
    int n = ntl * 8 + (lane >> 2);
    int k = ksg * 16 + (lane & 3) * 2 + j * 8;
    const float* wr = (l == 0) ? wr1 : (l == 1 ? wr2 : wr3);
    const float* wo = (l == 0) ? wo1 : (l == 1 ? wo2 : wo3);
    float v0, v1;
    if (k < 128) { v0 = wr[k * 128 + n];        v1 = wr[(k + 1) * 128 + n]; }
    else         { v0 = wo[(k - 128) * 128 + n]; v1 = wo[(k - 127) * 128 + n]; }
    __half2 h = __floats2half2_rn(v0, v1);
    ((uint32_t*)g_wtf)[i] = *(uint32_t*)&h;
}

// ---------------- aggregation: warp/node, 8-edge batches + col prefetch ------
__global__ void agg_kernel() {
    int gw   = (blockIdx.x * blockDim.x + threadIdx.x) >> 5;
    int lane = threadIdx.x & 31;
    if (gw >= NN) return;
    int beg = g_rowptr[gw];
    int end = g_rowptr[gw + 1];
    const uint2* hv = (const uint2*)g_hh;   // 32 uint2 per row
    const int l8 = lane & 7;
    float4 acc = make_float4(0.f, 0.f, 0.f, 0.f);
    int j = beg;
    int myc = 0;
    if (j + 8 <= end) myc = g_col[j + l8];
    for (; j + 8 <= end; j += 8) {
        int cur = myc;
        if (j + 16 <= end) myc = g_col[j + 8 + l8];   // prefetch next batch
        int s[8];
        #pragma unroll
        for (int e = 0; e < 8; e++) s[e] = __shfl_sync(0xFFFFFFFFu, cur, e);
        uint2 u[8];
        #pragma unroll
        for (int e = 0; e < 8; e++) u[e] = hv[(size_t)s[e] * 32 + lane];
        #pragma unroll
        for (int e = 0; e < 8; e++) {
            float2 a = __half22float2(*(__half2*)&u[e].x);
            float2 b = __half22float2(*(__half2*)&u[e].y);
            acc.x += a.x; acc.y += a.y; acc.z += b.x; acc.w += b.y;
        }
    }
    if (j < end) {
        int rem = end - j;   // 1..7
        int c = (l8 < rem) ? g_col[j + l8] : 0;
        for (int e = 0; e < rem; e++) {
            int s = __shfl_sync(0xFFFFFFFFu, c, e);
            uint2 u = hv[(size_t)s * 32 + lane];
            float2 a = __half22float2(*(__half2*)&u.x);
            float2 b = __half22float2(*(__half2*)&u.y);
            acc.x += a.x; acc.y += a.y; acc.z += b.x; acc.w += b.y;
        }
    }
    __half2 h0 = __floats2half2_rn(acc.x, acc.y);
    __half2 h1 = __floats2half2_rn(acc.z, acc.w);
    ((uint2*)g_aggh)[(size_t)gw * 32 + lane] = make_uint2(*(uint32_t*)&h0, *(uint32_t*)&h1);
}

// ---------------- fp16 GEMM: cp.async + ldmatrix + paired uint4 B loads ------
template <bool LAST>
__global__ void __launch_bounds__(256, 2)
gemm_mma_kernel(int layer, const float* __restrict__ bias, float* __restrict__ out)
{
    __shared__ __align__(16) uint8_t sA[2][128 * 128];

    const int tid  = threadIdx.x;
    const int lane = tid & 31;
    const int wid  = tid >> 5;
    const int wm   = wid & 3;     // 0..3  -> M
    const int wn   = wid >> 2;    // 0..1  -> N
    const int m0   = blockIdx.x * 128;
    const uint4* wtf4 = (const uint4*)(g_wtf + layer * 8192);
    const uint32_t sbase = smem_u32(sA);

    float acc[2][8][4];
    #pragma unroll
    for (int i = 0; i < 2; i++)
        #pragma unroll
        for (int j = 0; j < 8; j++)
            #pragma unroll
            for (int k = 0; k < 4; k++) acc[i][j][k] = 0.f;

    auto stage = [&](int c) {
        const __half* Asrc = (c < 2) ? g_aggh : g_hh;
        const uint8_t* base = (const uint8_t*)Asrc;
        const int cc = (c & 1) * 128;
        const uint32_t bufb = sbase + (uint32_t)(c & 1) * (128 * 128);
        #pragma unroll
        for (int it = 0; it < 4; it++) {
            int idx = it * 256 + tid;
            int r = idx >> 3, u = idx & 7;
            uint32_t dst = bufb + r * 128 + ((u ^ (r & 7)) * 16);
            const uint8_t* src = base + (size_t)(m0 + r) * 256 + cc + u * 16;
            int sz = (m0 + r < NN) ? 16 : 0;
            cp_async16(dst, src, sz);
        }
        asm volatile("cp.async.commit_group;" ::: "memory");
    };

    stage(0);

    #pragma unroll 1
    for (int c = 0; c < 4; c++) {
        if (c < 3) {
            stage(c + 1);
            asm volatile("cp.async.wait_group 1;" ::: "memory");
        } else {
            asm volatile("cp.async.wait_group 0;" ::: "memory");
        }
        __syncthreads();

        const uint32_t bufb = sbase + (uint32_t)(c & 1) * (128 * 128);
        #pragma unroll
        for (int ks = 0; ks < 4; ks++) {
            uint32_t a[2][4];
            #pragma unroll
            for (int mtl = 0; mtl < 2; mtl++) {
                int mt   = wm * 2 + mtl;
                int row  = mt * 16 + (lane & 15);
                int unit = 2 * ks + (lane >> 4);
                uint32_t addr = bufb + row * 128 + ((unit ^ (row & 7)) * 16);
                ldmatrix_x4(a[mtl], addr);
            }
            #pragma unroll
            for (int p = 0; p < 4; p++) {   // 4 n-tile pairs per warp
                uint4 bv = wtf4[(((c * 4 + ks) * 8) + wn * 4 + p) * 32 + lane];
                mma_f16(acc[0][2 * p + 0], a[0], bv.x, bv.y);
                mma_f16(acc[1][2 * p + 0], a[1], bv.x, bv.y);
                mma_f16(acc[0][2 * p + 1], a[0], bv.z, bv.w);
                mma_f16(acc[1][2 * p + 1], a[1], bv.z, bv.w);
            }
        }
        __syncthreads();
    }

    // ---- epilogue ----
    const int g   = lane >> 2;
    const int tig = lane & 3;
    #pragma unroll
    for (int mtl = 0; mtl < 2; mtl++) {
        #pragma unroll
        for (int h = 0; h < 2; h++) {
            int row = m0 + wm * 32 + mtl * 16 + h * 8 + g;
            if (row >= NN) continue;
            #pragma unroll
            for (int ntl = 0; ntl < 8; ntl++) {
                int col = wn * 64 + ntl * 8 + tig * 2;
                float ox = acc[mtl][ntl][h * 2 + 0] + __ldg(&bias[col + 0]);
                float oy = acc[mtl][ntl][h * 2 + 1] + __ldg(&bias[col + 1]);
                if (!LAST) {
                    ox = fmaxf(ox, 0.f); oy = fmaxf(oy, 0.f);
                    __half2 hh = __floats2half2_rn(ox, oy);
                    *(__half2*)&g_hh[(size_t)row * 128 + col] = hh;
                } else {
                    *(float2*)&out[(size_t)row * 128 + col] = make_float2(ox, oy);
                }
            }
        }
    }
}

// ---------------- launch ------------------------------------------------------
extern "C" void kernel_launch(void* const* d_in, const int* in_sizes, int n_in,
                              void* d_out, int out_size) {
    const float* x       = (const float*)d_in[0];
    const int*   ei      = (const int*)d_in[1];
    const float* w_rel1  = (const float*)d_in[2];
    const float* w_root1 = (const float*)d_in[3];
    const float* b1      = (const float*)d_in[4];
    const float* w_rel2  = (const float*)d_in[5];
    const float* w_root2 = (const float*)d_in[6];
    const float* b2      = (const float*)d_in[7];
    const float* w_rel3  = (const float*)d_in[8];
    const float* w_root3 = (const float*)d_in[9];
    const float* b3      = (const float*)d_in[10];
    float*       out     = (float*)d_out;

    const int AB = ((NN * 32) + 255) / 256;     // 12500 (warp per node)
    const int GB = (NN + 127) / 128;            // 782
    const int CB = (NN * D / 4 + 255) / 256;    // 12500

    cvt_x_kernel<<<CB, 256>>>(x);               // fp16 copy + cursor/sync zero
    csr_kernel<<<CSR_BLOCKS, 1024>>>(ei);       // fused hist+scan+fill

    // layer 1
    agg_kernel<<<AB, 256>>>();
    prep_wt_kernel<<<192, 256>>>(w_rel1, w_root1, w_rel2, w_root2, w_rel3, w_root3);
    gemm_mma_kernel<false><<<GB, 256>>>(0, b1, nullptr);
    // layer 2
    agg_kernel<<<AB, 256>>>();
    gemm_mma_kernel<false><<<GB, 256>>>(1, b2, nullptr);
    // layer 3 (no relu) -> d_out
    agg_kernel<<<AB, 256>>>();
    gemm_mma_kernel<true><<<GB, 256>>>(2, b3, out);
}